// round 1
// baseline (speedup 1.0000x reference)
#include <cuda_runtime.h>
#include <math.h>

// Fixed inner dims for this problem instance (e1=e2=c=m=1024); a,b derived at launch.
constexpr int KDIM = 1024;
constexpr int A_MAX = 8192;

// Scratch (device globals: allowed; runtime allocation is not)
static __device__ float g_p1[(size_t)A_MAX * KDIM];     // elu(seq1@W1.T + b1 + cvec1)
static __device__ float g_p2[(size_t)A_MAX * KDIM];
static __device__ float g_cvec[2 * KDIM];               // bias + Wc@ctx per branch
static __device__ float g_s[2 * KDIM];                  // column sums of p1 / p2
static __device__ float g_logits[2 * A_MAX];
static __device__ float g_w[2 * A_MAX];                 // softmax weights

// ---------------------------------------------------------------------------
__global__ void k_init(float* out, int out_n) {
    int i = blockIdx.x * blockDim.x + threadIdx.x;
    if (i < 2 * KDIM) g_s[i] = 0.f;
    if (i < out_n)    out[i] = 0.f;
}

// cvec[which][j] = bias[j] + dot(Wc[j,:], ctx)   (one warp per j)
__global__ void k_cvec(const float* __restrict__ Wc, const float* __restrict__ ctx,
                       const float* __restrict__ bias, int which) {
    int warp = (blockIdx.x * blockDim.x + threadIdx.x) >> 5;
    int lane = threadIdx.x & 31;
    if (warp >= KDIM) return;
    const float4* wrow = (const float4*)(Wc + (size_t)warp * KDIM);
    const float4* c4   = (const float4*)ctx;
    float sum = 0.f;
#pragma unroll
    for (int it = 0; it < KDIM / 128; ++it) {
        float4 wv = wrow[lane + it * 32];
        float4 cv = c4[lane + it * 32];
        sum += wv.x * cv.x + wv.y * cv.y + wv.z * cv.z + wv.w * cv.w;
    }
#pragma unroll
    for (int o = 16; o; o >>= 1) sum += __shfl_xor_sync(0xffffffffu, sum, o);
    if (lane == 0) g_cvec[which * KDIM + warp] = sum + bias[warp];
}

// P = elu(S @ W.T + cvec[which]); also accumulate column sums into g_s[which].
// Classic fp32 tiled GEMM: BM=BN=128, BK=8, 256 threads, 8x8 microtile.
__global__ __launch_bounds__(256)
void k_proj(const float* __restrict__ S, const float* __restrict__ W, int which) {
    constexpr int BM = 128, BN = 128, BK = 8, TM = 8, TN = 8;
    __shared__ float As[BK][BM + 4];
    __shared__ float Bs[BK][BN + 4];
    __shared__ float red[16][BN];

    float* __restrict__ P   = which ? g_p2 : g_p1;
    const float* __restrict__ cvec = g_cvec + which * KDIM;
    float* __restrict__ scol = g_s + which * KDIM;

    const int tid = threadIdx.x;
    const int rowBase = blockIdx.y * BM;
    const int colBase = blockIdx.x * BN;

    const int lrow = tid >> 1;          // 0..127
    const int lk4  = (tid & 1) * 4;     // 0 or 4
    const float* Sp = S + (size_t)(rowBase + lrow) * KDIM + lk4;
    const float* Wp = W + (size_t)(colBase + lrow) * KDIM + lk4;

    const int ty = tid >> 4, tx = tid & 15;
    const int tm = ty * TM, tn = tx * TN;

    float acc[TM][TN] = {};

    for (int kb = 0; kb < KDIM; kb += BK) {
        float4 av = *(const float4*)(Sp + kb);
        float4 bv = *(const float4*)(Wp + kb);
        As[lk4 + 0][lrow] = av.x; As[lk4 + 1][lrow] = av.y;
        As[lk4 + 2][lrow] = av.z; As[lk4 + 3][lrow] = av.w;
        Bs[lk4 + 0][lrow] = bv.x; Bs[lk4 + 1][lrow] = bv.y;
        Bs[lk4 + 2][lrow] = bv.z; Bs[lk4 + 3][lrow] = bv.w;
        __syncthreads();
#pragma unroll
        for (int k = 0; k < BK; ++k) {
            float a[TM], b[TN];
#pragma unroll
            for (int i = 0; i < TM; ++i) a[i] = As[k][tm + i];
#pragma unroll
            for (int j = 0; j < TN; ++j) b[j] = Bs[k][tn + j];
#pragma unroll
            for (int i = 0; i < TM; ++i)
#pragma unroll
                for (int j = 0; j < TN; ++j)
                    acc[i][j] += a[i] * b[j];
        }
        __syncthreads();
    }

    // Epilogue: +cvec, ELU, store P, partial column sums
    float cv[TN];
#pragma unroll
    for (int j = 0; j < TN; ++j) cv[j] = cvec[colBase + tn + j];

    float cpart[TN] = {};
#pragma unroll
    for (int i = 0; i < TM; ++i) {
        float* prow = P + (size_t)(rowBase + tm + i) * KDIM + colBase + tn;
#pragma unroll
        for (int j = 0; j < TN; ++j) {
            float v = acc[i][j] + cv[j];
            v = (v > 0.f) ? v : (expf(v) - 1.f);
            prow[j] = v;
            cpart[j] += v;
        }
    }
#pragma unroll
    for (int j = 0; j < TN; ++j) red[ty][tn + j] = cpart[j];
    __syncthreads();
    if (tid < BN) {
        float s = 0.f;
#pragma unroll
        for (int r = 0; r < 16; ++r) s += red[r][tid];
        atomicAdd(&scol[colBase + tid], s);
    }
}

// logits[whichL][i] = dot(P[whichP][i,:], g_s[whichS])   (one warp per row)
__global__ void k_matvec(int whichP, int whichS, int whichL, int M) {
    int warp = (blockIdx.x * blockDim.x + threadIdx.x) >> 5;
    int lane = threadIdx.x & 31;
    if (warp >= M) return;
    const float* P = whichP ? g_p2 : g_p1;
    const float4* pr = (const float4*)(P + (size_t)warp * KDIM);
    const float4* s4 = (const float4*)(g_s + whichS * KDIM);
    float sum = 0.f;
#pragma unroll
    for (int it = 0; it < KDIM / 128; ++it) {
        float4 p = pr[lane + it * 32];
        float4 q = s4[lane + it * 32];
        sum += p.x * q.x + p.y * q.y + p.z * q.z + p.w * q.w;
    }
#pragma unroll
    for (int o = 16; o; o >>= 1) sum += __shfl_xor_sync(0xffffffffu, sum, o);
    if (lane == 0) g_logits[whichL * A_MAX + warp] = sum;
}

// softmax over n logits -> weights (single block, 1024 threads)
__global__ void k_softmax(int which, int n) {
    __shared__ float sbuf[1024];
    const float* logits = g_logits + which * A_MAX;
    float* w = g_w + which * A_MAX;
    int tid = threadIdx.x;

    float mx = -3.4e38f;
    for (int i = tid; i < n; i += 1024) mx = fmaxf(mx, logits[i]);
    sbuf[tid] = mx; __syncthreads();
    for (int o = 512; o; o >>= 1) {
        if (tid < o) sbuf[tid] = fmaxf(sbuf[tid], sbuf[tid + o]);
        __syncthreads();
    }
    mx = sbuf[0]; __syncthreads();

    float se = 0.f;
    for (int i = tid; i < n; i += 1024) se += expf(logits[i] - mx);
    sbuf[tid] = se; __syncthreads();
    for (int o = 512; o; o >>= 1) {
        if (tid < o) sbuf[tid] += sbuf[tid + o];
        __syncthreads();
    }
    float inv = 1.f / sbuf[0];

    for (int i = tid; i < n; i += 1024) w[i] = expf(logits[i] - mx) * inv;
}

// out[col] += sum_r w[r] * seq[r, col]  over this block's row chunk
__global__ void k_pool(const float* __restrict__ seq, int which,
                       float* __restrict__ out, int rowsPerBlock) {
    const float* w = g_w + which * A_MAX;
    int col = blockIdx.x * blockDim.x + threadIdx.x;   // 0..KDIM-1
    int r0 = blockIdx.y * rowsPerBlock;
    float acc = 0.f;
    for (int r = r0; r < r0 + rowsPerBlock; ++r)
        acc += w[r] * seq[(size_t)r * KDIM + col];
    atomicAdd(&out[col], acc);
}

// ---------------------------------------------------------------------------
extern "C" void kernel_launch(void* const* d_in, const int* in_sizes, int n_in,
                              void* d_out, int out_size) {
    const float* seq1 = (const float*)d_in[0];
    const float* seq2 = (const float*)d_in[1];
    const float* ctx  = (const float*)d_in[2];
    const float* Wc1  = (const float*)d_in[3];
    const float* W1   = (const float*)d_in[4];
    const float* b1   = (const float*)d_in[5];
    const float* Wc2  = (const float*)d_in[6];
    const float* W2   = (const float*)d_in[7];
    const float* b2   = (const float*)d_in[8];
    float* out = (float*)d_out;

    const int a = in_sizes[0] / KDIM;   // 8192
    const int b = in_sizes[1] / KDIM;   // 8192

    k_init<<<(2 * KDIM + 255) / 256, 256>>>(out, out_size);

    k_cvec<<<KDIM / 8, 256>>>(Wc1, ctx, b1, 0);
    k_cvec<<<KDIM / 8, 256>>>(Wc2, ctx, b2, 1);

    {   // projections: grid (N/128, M/128)
        dim3 g1(KDIM / 128, a / 128), g2(KDIM / 128, b / 128);
        k_proj<<<g1, 256>>>(seq1, W1, 0);
        k_proj<<<g2, 256>>>(seq2, W2, 1);
    }

    // logits_a = p1 @ s2 ; logits_b = p2 @ s1
    k_matvec<<<(a + 7) / 8, 256>>>(0, 1, 0, a);
    k_matvec<<<(b + 7) / 8, 256>>>(1, 0, 1, b);

    k_softmax<<<1, 1024>>>(0, a);
    k_softmax<<<1, 1024>>>(1, b);

    {   // pools: grid (cols/256, rowChunks)
        const int RPB = 512;
        dim3 gp1(KDIM / 256, a / RPB), gp2(KDIM / 256, b / RPB);
        k_pool<<<gp1, 256>>>(seq1, 0, out, RPB);
        k_pool<<<gp2, 256>>>(seq2, 1, out + KDIM, RPB);
    }
}

// round 3
// speedup vs baseline: 2.0569x; 2.0569x over previous
#include <cuda_runtime.h>
#include <cuda_bf16.h>
#include <math.h>
#include <stdint.h>

// ---------------------------------------------------------------------------
// Problem dims (fixed for this instance): a=b=8192, e1=e2=c=m=1024
constexpr int KDIM = 1024;
constexpr int A_MAX = 8192;

constexpr int BM = 128;            // CTA M tile
constexpr int BN = 128;            // CTA N tile
constexpr int KC = 64;             // K chunk
constexpr int NCHUNK = KDIM / KC;  // 16
constexpr int SA = 72;             // SMEM row stride in bf16 elems (144B, conflict-free)
constexpr int TILE_B = BM * SA * 2;  // bytes per tile (18432)

// ---------------------------------------------------------------------------
// Device-global scratch
static __device__ __nv_bfloat16 g_p1[(size_t)A_MAX * KDIM];
static __device__ __nv_bfloat16 g_p2[(size_t)A_MAX * KDIM];
static __device__ float g_cvec[2 * KDIM];
static __device__ float g_s[2 * KDIM];
static __device__ float g_logits[2 * A_MAX];
static __device__ float g_w[2 * A_MAX];

// ---------------------------------------------------------------------------
__device__ __forceinline__ uint32_t smem_u32(const void* p) {
    uint32_t a;
    asm("{ .reg .u64 t; cvta.to.shared.u64 t, %1; cvt.u32.u64 %0, t; }" : "=r"(a) : "l"(p));
    return a;
}
__device__ __forceinline__ uint32_t lds32(uint32_t addr) {
    uint32_t v;
    asm volatile("ld.shared.b32 %0, [%1];" : "=r"(v) : "r"(addr));
    return v;
}
__device__ __forceinline__ void sts64(uint32_t addr, uint32_t v0, uint32_t v1) {
    asm volatile("st.shared.v2.b32 [%0], {%1, %2};" :: "r"(addr), "r"(v0), "r"(v1) : "memory");
}
__device__ __forceinline__ void mma16816(float* d, const uint32_t* a, const uint32_t* b) {
    asm volatile(
        "mma.sync.aligned.m16n8k16.row.col.f32.bf16.bf16.f32 "
        "{%0,%1,%2,%3}, {%4,%5,%6,%7}, {%8,%9}, {%0,%1,%2,%3};\n"
        : "+f"(d[0]), "+f"(d[1]), "+f"(d[2]), "+f"(d[3])
        : "r"(a[0]), "r"(a[1]), "r"(a[2]), "r"(a[3]), "r"(b[0]), "r"(b[1]));
}
__device__ __forceinline__ void split_pack(const float4& v, uint32_t& h0, uint32_t& h1,
                                           uint32_t& l0, uint32_t& l1) {
    float f[4] = {v.x, v.y, v.z, v.w};
    __nv_bfloat16 h[4], l[4];
#pragma unroll
    for (int j = 0; j < 4; ++j) {
        h[j] = __float2bfloat16_rn(f[j]);
        l[j] = __float2bfloat16_rn(f[j] - __bfloat162float(h[j]));
    }
    h0 = (uint32_t)__bfloat16_as_ushort(h[0]) | ((uint32_t)__bfloat16_as_ushort(h[1]) << 16);
    h1 = (uint32_t)__bfloat16_as_ushort(h[2]) | ((uint32_t)__bfloat16_as_ushort(h[3]) << 16);
    l0 = (uint32_t)__bfloat16_as_ushort(l[0]) | ((uint32_t)__bfloat16_as_ushort(l[1]) << 16);
    l1 = (uint32_t)__bfloat16_as_ushort(l[2]) | ((uint32_t)__bfloat16_as_ushort(l[3]) << 16);
}

// ---------------------------------------------------------------------------
__global__ void k_init(float* out, int out_n) {
    int i = blockIdx.x * blockDim.x + threadIdx.x;
    if (i < 2 * KDIM) g_s[i] = 0.f;
    if (i < out_n)    out[i] = 0.f;
}

// cvec[which][j] = bias[j] + dot(Wc[j,:], ctx)
__global__ void k_cvec(const float* __restrict__ Wc, const float* __restrict__ ctx,
                       const float* __restrict__ bias, int which) {
    int warp = (blockIdx.x * blockDim.x + threadIdx.x) >> 5;
    int lane = threadIdx.x & 31;
    if (warp >= KDIM) return;
    const float4* wrow = (const float4*)(Wc + (size_t)warp * KDIM);
    const float4* c4   = (const float4*)ctx;
    float sum = 0.f;
#pragma unroll
    for (int it = 0; it < KDIM / 128; ++it) {
        float4 wv = wrow[lane + it * 32];
        float4 cv = c4[lane + it * 32];
        sum += wv.x * cv.x + wv.y * cv.y + wv.z * cv.z + wv.w * cv.w;
    }
#pragma unroll
    for (int o = 16; o; o >>= 1) sum += __shfl_xor_sync(0xffffffffu, sum, o);
    if (lane == 0) g_cvec[which * KDIM + warp] = sum + bias[warp];
}

// ---------------------------------------------------------------------------
// P = elu(S @ W.T + cvec), split-bf16 3-MMA emulation via mma.sync.m16n8k16.
// 512 threads = 16 warps (4x4 warp grid, 32x32 per warp). blockIdx.z = branch.
__global__ __launch_bounds__(512)
void k_proj_mma(const float* __restrict__ S1, const float* __restrict__ W1,
                const float* __restrict__ S2, const float* __restrict__ W2) {
    extern __shared__ char dynsm[];
    const uint32_t sb = smem_u32(dynsm);
    const uint32_t smAh = sb;
    const uint32_t smAl = sb + TILE_B;
    const uint32_t smBh = sb + 2 * TILE_B;
    const uint32_t smBl = sb + 3 * TILE_B;

    const int which = blockIdx.z;
    const float* __restrict__ S = which ? S2 : S1;
    const float* __restrict__ W = which ? W2 : W1;
    __nv_bfloat16* __restrict__ P = which ? g_p2 : g_p1;
    const float* __restrict__ cvec = g_cvec + which * KDIM;
    float* __restrict__ scol = g_s + which * KDIM;

    const int tid  = threadIdx.x;
    const int wid  = tid >> 5;
    const int lane = tid & 31;
    const int warpRow = wid & 3;       // 0..3 -> rows 32*warpRow
    const int warpCol = wid >> 2;      // 0..3 -> cols 32*warpCol
    const int rowBase = blockIdx.y * BM;
    const int colBase = blockIdx.x * BN;

    // Global-load mapping: chunk = 128 rows x 16 float4. idx = tid + i*512, i=0..3
    // row = idx>>4, c4 = idx&15
    const int gr = tid >> 4;           // base row for i=0 (rows advance by 32 per i)
    const int gc4 = tid & 15;
    const float* Sp = S + (size_t)(rowBase + gr) * KDIM + gc4 * 4;
    const float* Wp = W + (size_t)(colBase + gr) * KDIM + gc4 * 4;

    float4 a4[4], b4[4];
#pragma unroll
    for (int i = 0; i < 4; ++i) {
        a4[i] = *(const float4*)(Sp + (size_t)(32 * i) * KDIM);
        b4[i] = *(const float4*)(Wp + (size_t)(32 * i) * KDIM);
    }

    float acc[2][4][4];  // [rowblk][colfrag][reg]
#pragma unroll
    for (int rb = 0; rb < 2; ++rb)
#pragma unroll
        for (int cf = 0; cf < 4; ++cf)
#pragma unroll
            for (int r = 0; r < 4; ++r) acc[rb][cf][r] = 0.f;

    // Fragment LDS addresses
    const int gq  = lane >> 2;         // group id 0..7
    const int tig = lane & 3;          // thread in group
    // A frags: rows warpRow*32 + rb*16 + gq (+8); k = ks*16 + tig*2 (+8)
    // B frags: col  warpCol*32 + cf*8 + gq;       k same
    const uint32_t aRowOff0 = (uint32_t)(warpRow * 32 + gq) * (SA * 2);
    const uint32_t bColOff0 = (uint32_t)(warpCol * 32 + gq) * (SA * 2);
    const uint32_t kOffB = (uint32_t)(tig * 2) * 2;  // bytes within row

    for (int c = 0; c < NCHUNK; ++c) {
        // ---- convert + STS (single buffer) ----
        __syncthreads();  // protect SMEM from previous chunk's readers
#pragma unroll
        for (int i = 0; i < 4; ++i) {
            uint32_t off = (uint32_t)(gr + 32 * i) * (SA * 2) + (uint32_t)gc4 * 8;
            uint32_t h0, h1, l0, l1;
            split_pack(a4[i], h0, h1, l0, l1);
            sts64(smAh + off, h0, h1);
            sts64(smAl + off, l0, l1);
            split_pack(b4[i], h0, h1, l0, l1);
            sts64(smBh + off, h0, h1);
            sts64(smBl + off, l0, l1);
        }
        __syncthreads();

        // ---- prefetch next chunk (LDG latency hides behind MMAs) ----
        if (c + 1 < NCHUNK) {
            int kb = (c + 1) * KC;
#pragma unroll
            for (int i = 0; i < 4; ++i) {
                a4[i] = *(const float4*)(Sp + (size_t)(32 * i) * KDIM + kb);
                b4[i] = *(const float4*)(Wp + (size_t)(32 * i) * KDIM + kb);
            }
        }

        // ---- MMAs over 4 k-steps of 16 ----
#pragma unroll
        for (int ks = 0; ks < 4; ++ks) {
            const uint32_t kByte = (uint32_t)(ks * 16) * 2 + kOffB;
            uint32_t ah[2][4], al[2][4];
#pragma unroll
            for (int rb = 0; rb < 2; ++rb) {
                uint32_t ro = aRowOff0 + (uint32_t)(rb * 16) * (SA * 2);
                ah[rb][0] = lds32(smAh + ro + kByte);
                ah[rb][1] = lds32(smAh + ro + 8 * (SA * 2) + kByte);
                ah[rb][2] = lds32(smAh + ro + kByte + 16);
                ah[rb][3] = lds32(smAh + ro + 8 * (SA * 2) + kByte + 16);
                al[rb][0] = lds32(smAl + ro + kByte);
                al[rb][1] = lds32(smAl + ro + 8 * (SA * 2) + kByte);
                al[rb][2] = lds32(smAl + ro + kByte + 16);
                al[rb][3] = lds32(smAl + ro + 8 * (SA * 2) + kByte + 16);
            }
#pragma unroll
            for (int cf = 0; cf < 4; ++cf) {
                uint32_t co = bColOff0 + (uint32_t)(cf * 8) * (SA * 2);
                uint32_t bh[2], bl[2];
                bh[0] = lds32(smBh + co + kByte);
                bh[1] = lds32(smBh + co + kByte + 16);
                bl[0] = lds32(smBl + co + kByte);
                bl[1] = lds32(smBl + co + kByte + 16);
#pragma unroll
                for (int rb = 0; rb < 2; ++rb) {
                    mma16816(acc[rb][cf], ah[rb], bh);
                    mma16816(acc[rb][cf], ah[rb], bl);
                    mma16816(acc[rb][cf], al[rb], bh);
                }
            }
        }
    }

    // ---- epilogue: +cvec, ELU, bf16 store, column sums ----
    float csum[8];
#pragma unroll
    for (int j = 0; j < 8; ++j) csum[j] = 0.f;

#pragma unroll
    for (int rb = 0; rb < 2; ++rb) {
#pragma unroll
        for (int cf = 0; cf < 4; ++cf) {
            const int col = colBase + warpCol * 32 + cf * 8 + tig * 2;
            const float cv0 = cvec[col], cv1 = cvec[col + 1];
#pragma unroll
            for (int half = 0; half < 2; ++half) {
                const int row = rowBase + warpRow * 32 + rb * 16 + gq + half * 8;
                float v0 = acc[rb][cf][half * 2 + 0] + cv0;
                float v1 = acc[rb][cf][half * 2 + 1] + cv1;
                v0 = (v0 > 0.f) ? v0 : expm1f(v0);
                v1 = (v1 > 0.f) ? v1 : expm1f(v1);
                __nv_bfloat162 pk;
                pk.x = __float2bfloat16_rn(v0);
                pk.y = __float2bfloat16_rn(v1);
                *(__nv_bfloat162*)(P + (size_t)row * KDIM + col) = pk;
                csum[cf * 2 + 0] += v0;
                csum[cf * 2 + 1] += v1;
            }
        }
    }
    // reduce csum across lanes sharing (lane&3): xor 4, 8, 16
#pragma unroll
    for (int j = 0; j < 8; ++j) {
        float v = csum[j];
        v += __shfl_xor_sync(0xffffffffu, v, 4);
        v += __shfl_xor_sync(0xffffffffu, v, 8);
        v += __shfl_xor_sync(0xffffffffu, v, 16);
        if (gq == 0) {
            int col = colBase + warpCol * 32 + (j >> 1) * 8 + tig * 2 + (j & 1);
            atomicAdd(&scol[col], v);
        }
    }
}

// ---------------------------------------------------------------------------
// logits[whichL][i] = dot(P[whichP][i,:], g_s[whichS])  (one warp per row, bf16 P)
__global__ void k_matvec(int whichP, int whichS, int whichL, int M) {
    int warp = (blockIdx.x * blockDim.x + threadIdx.x) >> 5;
    int lane = threadIdx.x & 31;
    if (warp >= M) return;
    const __nv_bfloat16* P = whichP ? g_p2 : g_p1;
    const uint4* pr = (const uint4*)(P + (size_t)warp * KDIM);
    const float4* s4 = (const float4*)(g_s + whichS * KDIM);
    float sum = 0.f;
#pragma unroll
    for (int it = 0; it < KDIM / 256; ++it) {
        uint4 pk = pr[lane + it * 32];
        float4 sa = s4[(lane + it * 32) * 2 + 0];
        float4 sbv = s4[(lane + it * 32) * 2 + 1];
        float2 p0 = __bfloat1622float2(*(const __nv_bfloat162*)&pk.x);
        float2 p1 = __bfloat1622float2(*(const __nv_bfloat162*)&pk.y);
        float2 p2 = __bfloat1622float2(*(const __nv_bfloat162*)&pk.z);
        float2 p3 = __bfloat1622float2(*(const __nv_bfloat162*)&pk.w);
        sum += p0.x * sa.x + p0.y * sa.y + p1.x * sa.z + p1.y * sa.w;
        sum += p2.x * sbv.x + p2.y * sbv.y + p3.x * sbv.z + p3.y * sbv.w;
    }
#pragma unroll
    for (int o = 16; o; o >>= 1) sum += __shfl_xor_sync(0xffffffffu, sum, o);
    if (lane == 0) g_logits[whichL * A_MAX + warp] = sum;
}

// softmax over n logits -> weights
__global__ void k_softmax(int which, int n) {
    __shared__ float sbuf[1024];
    const float* logits = g_logits + which * A_MAX;
    float* w = g_w + which * A_MAX;
    int tid = threadIdx.x;

    float mx = -3.4e38f;
    for (int i = tid; i < n; i += 1024) mx = fmaxf(mx, logits[i]);
    sbuf[tid] = mx; __syncthreads();
    for (int o = 512; o; o >>= 1) {
        if (tid < o) sbuf[tid] = fmaxf(sbuf[tid], sbuf[tid + o]);
        __syncthreads();
    }
    mx = sbuf[0]; __syncthreads();

    float se = 0.f;
    for (int i = tid; i < n; i += 1024) se += expf(logits[i] - mx);
    sbuf[tid] = se; __syncthreads();
    for (int o = 512; o; o >>= 1) {
        if (tid < o) sbuf[tid] += sbuf[tid + o];
        __syncthreads();
    }
    float inv = 1.f / sbuf[0];

    for (int i = tid; i < n; i += 1024) w[i] = expf(logits[i] - mx) * inv;
}

// out[col] += sum_r w[r] * seq[r, col]
__global__ void k_pool(const float* __restrict__ seq, int which,
                       float* __restrict__ out, int rowsPerBlock) {
    const float* w = g_w + which * A_MAX;
    int col = blockIdx.x * blockDim.x + threadIdx.x;
    int r0 = blockIdx.y * rowsPerBlock;
    float acc = 0.f;
    for (int r = r0; r < r0 + rowsPerBlock; ++r)
        acc += w[r] * seq[(size_t)r * KDIM + col];
    atomicAdd(&out[col], acc);
}

// ---------------------------------------------------------------------------
extern "C" void kernel_launch(void* const* d_in, const int* in_sizes, int n_in,
                              void* d_out, int out_size) {
    const float* seq1 = (const float*)d_in[0];
    const float* seq2 = (const float*)d_in[1];
    const float* ctx  = (const float*)d_in[2];
    const float* Wc1  = (const float*)d_in[3];
    const float* W1   = (const float*)d_in[4];
    const float* b1   = (const float*)d_in[5];
    const float* Wc2  = (const float*)d_in[6];
    const float* W2   = (const float*)d_in[7];
    const float* b2   = (const float*)d_in[8];
    float* out = (float*)d_out;

    const int a = in_sizes[0] / KDIM;   // 8192
    const int b = in_sizes[1] / KDIM;   // 8192

    static bool attrSet = false;
    if (!attrSet) {
        cudaFuncSetAttribute(k_proj_mma, cudaFuncAttributeMaxDynamicSharedMemorySize,
                             4 * TILE_B);
        attrSet = true;
    }

    k_init<<<(2 * KDIM + 255) / 256, 256>>>(out, out_size);

    k_cvec<<<KDIM / 8, 256>>>(Wc1, ctx, b1, 0);
    k_cvec<<<KDIM / 8, 256>>>(Wc2, ctx, b2, 1);

    {   // both projections, one launch: grid (N/128, M/128, 2)
        dim3 g(KDIM / BN, a / BM, 2);
        k_proj_mma<<<g, 512, 4 * TILE_B>>>(seq1, W1, seq2, W2);
    }

    k_matvec<<<(a + 7) / 8, 256>>>(0, 1, 0, a);
    k_matvec<<<(b + 7) / 8, 256>>>(1, 0, 1, b);

    k_softmax<<<1, 1024>>>(0, a);
    k_softmax<<<1, 1024>>>(1, b);

    {
        const int RPB = 512;
        dim3 gp1(KDIM / 256, a / RPB), gp2(KDIM / 256, b / RPB);
        k_pool<<<gp1, 256>>>(seq1, 0, out, RPB);
        k_pool<<<gp2, 256>>>(seq2, 1, out + KDIM, RPB);
    }
}

// round 4
// speedup vs baseline: 4.3720x; 2.1255x over previous
#include <cuda_runtime.h>
#include <cuda_bf16.h>
#include <math.h>
#include <stdint.h>

// ---------------------------------------------------------------------------
// Problem dims (fixed): a=b=8192, e1=e2=c=m=1024
constexpr int KDIM = 1024;
constexpr int A_MAX = 8192;

constexpr int BM = 128;
constexpr int BN = 128;
constexpr int KC = 64;               // K chunk (bf16)
constexpr int NCHUNK = KDIM / KC;    // 16
constexpr int SAB = 144;             // SMEM row stride bytes (72 bf16) — conflict-free
constexpr int TILE_B = BM * SAB;     // 18432 B per tile
constexpr int STAGE_B = 2 * TILE_B;  // A + B per stage
constexpr int SMEM_DYN = 2 * STAGE_B;  // double buffered: 73728 B

// ---------------------------------------------------------------------------
static __device__ __nv_bfloat16 g_p1[(size_t)A_MAX * KDIM];
static __device__ __nv_bfloat16 g_p2[(size_t)A_MAX * KDIM];
static __device__ float g_cvec[2 * KDIM];
static __device__ float g_s[2 * KDIM];
static __device__ float g_logits[2 * A_MAX];
static __device__ float g_w[2 * A_MAX];

// ---------------------------------------------------------------------------
__device__ __forceinline__ uint32_t smem_u32(const void* p) {
    uint32_t a;
    asm("{ .reg .u64 t; cvta.to.shared.u64 t, %1; cvt.u32.u64 %0, t; }" : "=r"(a) : "l"(p));
    return a;
}
__device__ __forceinline__ void sts64(uint32_t addr, uint32_t v0, uint32_t v1) {
    asm volatile("st.shared.v2.b32 [%0], {%1, %2};" :: "r"(addr), "r"(v0), "r"(v1) : "memory");
}
__device__ __forceinline__ void ldsm_x4(uint32_t addr, uint32_t* r) {
    asm volatile("ldmatrix.sync.aligned.m8n8.x4.shared.b16 {%0,%1,%2,%3}, [%4];"
                 : "=r"(r[0]), "=r"(r[1]), "=r"(r[2]), "=r"(r[3]) : "r"(addr));
}
__device__ __forceinline__ void mma16816(float* d, const uint32_t* a, const uint32_t* b) {
    asm volatile(
        "mma.sync.aligned.m16n8k16.row.col.f32.bf16.bf16.f32 "
        "{%0,%1,%2,%3}, {%4,%5,%6,%7}, {%8,%9}, {%0,%1,%2,%3};\n"
        : "+f"(d[0]), "+f"(d[1]), "+f"(d[2]), "+f"(d[3])
        : "r"(a[0]), "r"(a[1]), "r"(a[2]), "r"(a[3]), "r"(b[0]), "r"(b[1]));
}
__device__ __forceinline__ void pack_bf16(const float4& v, uint32_t& p0, uint32_t& p1) {
    __nv_bfloat162 x = __floats2bfloat162_rn(v.x, v.y);
    __nv_bfloat162 y = __floats2bfloat162_rn(v.z, v.w);
    p0 = *(uint32_t*)&x;
    p1 = *(uint32_t*)&y;
}

// ---------------------------------------------------------------------------
__global__ void k_init(float* out, int out_n) {
    int i = blockIdx.x * blockDim.x + threadIdx.x;
    if (i < 2 * KDIM) g_s[i] = 0.f;
    if (i < out_n)    out[i] = 0.f;
}

__global__ void k_cvec(const float* __restrict__ Wc, const float* __restrict__ ctx,
                       const float* __restrict__ bias, int which) {
    int warp = (blockIdx.x * blockDim.x + threadIdx.x) >> 5;
    int lane = threadIdx.x & 31;
    if (warp >= KDIM) return;
    const float4* wrow = (const float4*)(Wc + (size_t)warp * KDIM);
    const float4* c4   = (const float4*)ctx;
    float sum = 0.f;
#pragma unroll
    for (int it = 0; it < KDIM / 128; ++it) {
        float4 wv = wrow[lane + it * 32];
        float4 cv = c4[lane + it * 32];
        sum += wv.x * cv.x + wv.y * cv.y + wv.z * cv.z + wv.w * cv.w;
    }
#pragma unroll
    for (int o = 16; o; o >>= 1) sum += __shfl_xor_sync(0xffffffffu, sum, o);
    if (lane == 0) g_cvec[which * KDIM + warp] = sum + bias[warp];
}

// ---------------------------------------------------------------------------
// P = elu(S @ W.T + cvec). bf16 mma.sync, double-buffered SMEM, ldmatrix frags.
// 512 threads = 16 warps (4x4 warp grid, 32x32 per warp). blockIdx.z = branch.
__global__ __launch_bounds__(512)
void k_proj_mma(const float* __restrict__ S1, const float* __restrict__ W1,
                const float* __restrict__ S2, const float* __restrict__ W2) {
    extern __shared__ char dynsm[];
    const uint32_t sb = smem_u32(dynsm);

    const int which = blockIdx.z;
    const float* __restrict__ S = which ? S2 : S1;
    const float* __restrict__ W = which ? W2 : W1;
    __nv_bfloat16* __restrict__ P = which ? g_p2 : g_p1;
    const float* __restrict__ cvec = g_cvec + which * KDIM;
    float* __restrict__ scol = g_s + which * KDIM;

    const int tid  = threadIdx.x;
    const int wid  = tid >> 5;
    const int lane = tid & 31;
    const int warpRow = wid & 3;
    const int warpCol = wid >> 2;
    const int rowBase = blockIdx.y * BM;
    const int colBase = blockIdx.x * BN;

    // Global-load mapping: idx = tid + i*512; row = idx>>4 (advance 32/i), c4 = idx&15
    const int gr  = tid >> 4;
    const int gc4 = tid & 15;
    const float* Sp = S + (size_t)(rowBase + gr) * KDIM + gc4 * 4;
    const float* Wp = W + (size_t)(colBase + gr) * KDIM + gc4 * 4;

    float4 a4[4], b4[4];
#pragma unroll
    for (int i = 0; i < 4; ++i) {
        a4[i] = *(const float4*)(Sp + (size_t)(32 * i) * KDIM);
        b4[i] = *(const float4*)(Wp + (size_t)(32 * i) * KDIM);
    }

    float acc[2][4][4] = {};

    // ldmatrix addressing
    const int laneQ = lane & 7;
    const int blkId = lane >> 3;           // 0..3
    // A: row = warpRow*32 + rb*16 + (blk&1)*8 + laneQ ; kbyte = ks*32 + (blk>>1)*16
    const uint32_t aRow = (uint32_t)(warpRow * 32 + (blkId & 1) * 8 + laneQ);
    const uint32_t aKof = (uint32_t)((blkId >> 1) * 16);
    // B: row = warpCol*32 + (pair*16) + (blk>>1)*8 + laneQ ; kbyte = ks*32 + (blk&1)*16
    const uint32_t bRow = (uint32_t)(warpCol * 32 + (blkId >> 1) * 8 + laneQ);
    const uint32_t bKof = (uint32_t)((blkId & 1) * 16);

    const uint32_t stsOff = (uint32_t)gr * SAB + (uint32_t)gc4 * 8;

    // --- prologue: STS chunk 0 into stage 0 ---
#pragma unroll
    for (int i = 0; i < 4; ++i) {
        uint32_t p0, p1;
        pack_bf16(a4[i], p0, p1);
        sts64(sb + stsOff + (uint32_t)(32 * i) * SAB, p0, p1);
        pack_bf16(b4[i], p0, p1);
        sts64(sb + TILE_B + stsOff + (uint32_t)(32 * i) * SAB, p0, p1);
    }
    __syncthreads();

    uint32_t stage = 0;
    for (int c = 0; c < NCHUNK; ++c) {
        // prefetch next chunk from global
        if (c + 1 < NCHUNK) {
            const int kb = (c + 1) * KC;
#pragma unroll
            for (int i = 0; i < 4; ++i) {
                a4[i] = *(const float4*)(Sp + (size_t)(32 * i) * KDIM + kb);
                b4[i] = *(const float4*)(Wp + (size_t)(32 * i) * KDIM + kb);
            }
        }

        // MMAs from current stage
        const uint32_t smA = sb + stage * STAGE_B;
        const uint32_t smB = smA + TILE_B;
#pragma unroll
        for (int ks = 0; ks < 4; ++ks) {
            const uint32_t kByte = (uint32_t)(ks * 32);
            uint32_t af[2][4], bf[2][4];
#pragma unroll
            for (int rb = 0; rb < 2; ++rb)
                ldsm_x4(smA + (aRow + (uint32_t)(rb * 16)) * SAB + kByte + aKof, af[rb]);
#pragma unroll
            for (int pr = 0; pr < 2; ++pr)
                ldsm_x4(smB + (bRow + (uint32_t)(pr * 16)) * SAB + kByte + bKof, bf[pr]);
#pragma unroll
            for (int cf = 0; cf < 4; ++cf) {
                const uint32_t* bp = &bf[cf >> 1][(cf & 1) * 2];
#pragma unroll
                for (int rb = 0; rb < 2; ++rb)
                    mma16816(acc[rb][cf], af[rb], bp);
            }
        }

        // STS next chunk into other stage
        if (c + 1 < NCHUNK) {
            const uint32_t dA = sb + (stage ^ 1u) * STAGE_B;
#pragma unroll
            for (int i = 0; i < 4; ++i) {
                uint32_t p0, p1;
                pack_bf16(a4[i], p0, p1);
                sts64(dA + stsOff + (uint32_t)(32 * i) * SAB, p0, p1);
                pack_bf16(b4[i], p0, p1);
                sts64(dA + TILE_B + stsOff + (uint32_t)(32 * i) * SAB, p0, p1);
            }
        }
        __syncthreads();
        stage ^= 1u;
    }

    // ---- epilogue: +cvec, ELU, bf16 store, column sums ----
    const int gq  = lane >> 2;
    const int tig = lane & 3;
    float csum[8];
#pragma unroll
    for (int j = 0; j < 8; ++j) csum[j] = 0.f;

#pragma unroll
    for (int rb = 0; rb < 2; ++rb) {
#pragma unroll
        for (int cf = 0; cf < 4; ++cf) {
            const int col = colBase + warpCol * 32 + cf * 8 + tig * 2;
            const float cv0 = cvec[col], cv1 = cvec[col + 1];
#pragma unroll
            for (int half = 0; half < 2; ++half) {
                const int row = rowBase + warpRow * 32 + rb * 16 + gq + half * 8;
                float v0 = acc[rb][cf][half * 2 + 0] + cv0;
                float v1 = acc[rb][cf][half * 2 + 1] + cv1;
                v0 = (v0 > 0.f) ? v0 : expm1f(v0);
                v1 = (v1 > 0.f) ? v1 : expm1f(v1);
                __nv_bfloat162 pk = __floats2bfloat162_rn(v0, v1);
                *(__nv_bfloat162*)(P + (size_t)row * KDIM + col) = pk;
                csum[cf * 2 + 0] += v0;
                csum[cf * 2 + 1] += v1;
            }
        }
    }
#pragma unroll
    for (int j = 0; j < 8; ++j) {
        float v = csum[j];
        v += __shfl_xor_sync(0xffffffffu, v, 4);
        v += __shfl_xor_sync(0xffffffffu, v, 8);
        v += __shfl_xor_sync(0xffffffffu, v, 16);
        if (gq == 0) {
            int col = colBase + warpCol * 32 + (j >> 1) * 8 + tig * 2 + (j & 1);
            atomicAdd(&scol[col], v);
        }
    }
}

// ---------------------------------------------------------------------------
// logits[z][i] = dot(P[z][i,:], g_s[1-z])  (one warp per row; blockIdx.y = z)
__global__ void k_matvec(int M) {
    int warp = (blockIdx.x * blockDim.x + threadIdx.x) >> 5;
    int lane = threadIdx.x & 31;
    if (warp >= M) return;
    const int z = blockIdx.y;
    const __nv_bfloat16* P = z ? g_p2 : g_p1;
    const uint4* pr = (const uint4*)(P + (size_t)warp * KDIM);
    const float4* s4 = (const float4*)(g_s + (1 - z) * KDIM);
    float sum = 0.f;
#pragma unroll
    for (int it = 0; it < KDIM / 256; ++it) {
        uint4 pk = pr[lane + it * 32];
        float4 sa = s4[(lane + it * 32) * 2 + 0];
        float4 sbv = s4[(lane + it * 32) * 2 + 1];
        float2 p0 = __bfloat1622float2(*(const __nv_bfloat162*)&pk.x);
        float2 p1 = __bfloat1622float2(*(const __nv_bfloat162*)&pk.y);
        float2 p2 = __bfloat1622float2(*(const __nv_bfloat162*)&pk.z);
        float2 p3 = __bfloat1622float2(*(const __nv_bfloat162*)&pk.w);
        sum += p0.x * sa.x + p0.y * sa.y + p1.x * sa.z + p1.y * sa.w;
        sum += p2.x * sbv.x + p2.y * sbv.y + p3.x * sbv.z + p3.y * sbv.w;
    }
#pragma unroll
    for (int o = 16; o; o >>= 1) sum += __shfl_xor_sync(0xffffffffu, sum, o);
    if (lane == 0) g_logits[z * A_MAX + warp] = sum;
}

// softmax over n logits; blockIdx.x = which
__global__ void k_softmax(int n) {
    __shared__ float sbuf[1024];
    const int which = blockIdx.x;
    const float* logits = g_logits + which * A_MAX;
    float* w = g_w + which * A_MAX;
    int tid = threadIdx.x;

    float mx = -3.4e38f;
    for (int i = tid; i < n; i += 1024) mx = fmaxf(mx, logits[i]);
    sbuf[tid] = mx; __syncthreads();
    for (int o = 512; o; o >>= 1) {
        if (tid < o) sbuf[tid] = fmaxf(sbuf[tid], sbuf[tid + o]);
        __syncthreads();
    }
    mx = sbuf[0]; __syncthreads();

    float se = 0.f;
    for (int i = tid; i < n; i += 1024) se += expf(logits[i] - mx);
    sbuf[tid] = se; __syncthreads();
    for (int o = 512; o; o >>= 1) {
        if (tid < o) sbuf[tid] += sbuf[tid + o];
        __syncthreads();
    }
    float inv = 1.f / sbuf[0];

    for (int i = tid; i < n; i += 1024) w[i] = expf(logits[i] - mx) * inv;
}

// out[z*KDIM + col] += sum_r w[z][r] * seq_z[r, col]; blockIdx.z = z
__global__ void k_pool(const float* __restrict__ seq1, const float* __restrict__ seq2,
                       float* __restrict__ out, int rowsPerBlock) {
    const int z = blockIdx.z;
    const float* seq = z ? seq2 : seq1;
    const float* w = g_w + z * A_MAX;
    int col = blockIdx.x * blockDim.x + threadIdx.x;
    int r0 = blockIdx.y * rowsPerBlock;
    float acc = 0.f;
    for (int r = r0; r < r0 + rowsPerBlock; ++r)
        acc += w[r] * seq[(size_t)r * KDIM + col];
    atomicAdd(&out[z * KDIM + col], acc);
}

// ---------------------------------------------------------------------------
extern "C" void kernel_launch(void* const* d_in, const int* in_sizes, int n_in,
                              void* d_out, int out_size) {
    const float* seq1 = (const float*)d_in[0];
    const float* seq2 = (const float*)d_in[1];
    const float* ctx  = (const float*)d_in[2];
    const float* Wc1  = (const float*)d_in[3];
    const float* W1   = (const float*)d_in[4];
    const float* b1   = (const float*)d_in[5];
    const float* Wc2  = (const float*)d_in[6];
    const float* W2   = (const float*)d_in[7];
    const float* b2   = (const float*)d_in[8];
    float* out = (float*)d_out;

    const int a = in_sizes[0] / KDIM;   // 8192
    const int b = in_sizes[1] / KDIM;   // 8192

    static bool attrSet = false;
    if (!attrSet) {
        cudaFuncSetAttribute(k_proj_mma, cudaFuncAttributeMaxDynamicSharedMemorySize,
                             SMEM_DYN);
        attrSet = true;
    }

    k_init<<<(2 * KDIM + 255) / 256, 256>>>(out, out_size);

    k_cvec<<<KDIM / 8, 256>>>(Wc1, ctx, b1, 0);
    k_cvec<<<KDIM / 8, 256>>>(Wc2, ctx, b2, 1);

    {
        dim3 g(KDIM / BN, a / BM, 2);
        k_proj_mma<<<g, 512, SMEM_DYN>>>(seq1, W1, seq2, W2);
    }

    {
        dim3 gm((a + 7) / 8, 2);
        k_matvec<<<gm, 256>>>(a);
    }

    k_softmax<<<2, 1024>>>(a);

    {
        const int RPB = 512;
        dim3 gp(KDIM / 256, a / RPB, 2);
        k_pool<<<gp, 256>>>(seq1, seq2, out, RPB);
    }
}

// round 7
// speedup vs baseline: 6.2621x; 1.4323x over previous
#include <cuda_runtime.h>
#include <cuda_bf16.h>
#include <math.h>
#include <stdint.h>

// ---------------------------------------------------------------------------
// Problem dims (fixed): a=b=8192, e1=e2=c=m=1024
constexpr int KDIM = 1024;
constexpr int A_MAX = 8192;

constexpr int BM = 128;
constexpr int BN = 128;
constexpr int KC = 64;                  // K chunk (bf16): 128 B per row
constexpr int NCHUNK = KDIM / KC;       // 16
constexpr int TILE_B = BM * 128;        // 16384 B per tile (128B rows)
constexpr int STAGE_B = 2 * TILE_B;     // A + B per stage = 32768
constexpr int NSTAGE = 3;
constexpr int SMEM_DYN = NSTAGE * STAGE_B;  // 98304 B

// ---------------------------------------------------------------------------
// Device-global scratch
static __device__ __nv_bfloat16 g_x1[(size_t)A_MAX * KDIM];   // seq1 bf16
static __device__ __nv_bfloat16 g_x2[(size_t)A_MAX * KDIM];   // seq2 bf16
static __device__ __nv_bfloat16 g_wt1[(size_t)KDIM * KDIM];   // W1 bf16
static __device__ __nv_bfloat16 g_wt2[(size_t)KDIM * KDIM];   // W2 bf16
static __device__ __nv_bfloat16 g_p1[(size_t)A_MAX * KDIM];
static __device__ __nv_bfloat16 g_p2[(size_t)A_MAX * KDIM];
static __device__ float g_cvec[2 * KDIM];
static __device__ float g_s[2 * KDIM];
static __device__ float g_logits[2 * A_MAX];
static __device__ float g_w[2 * A_MAX];

// ---------------------------------------------------------------------------
__device__ __forceinline__ uint32_t smem_u32(const void* p) {
    uint32_t a;
    asm("{ .reg .u64 t; cvta.to.shared.u64 t, %1; cvt.u32.u64 %0, t; }" : "=r"(a) : "l"(p));
    return a;
}
__device__ __forceinline__ void cp16(uint32_t smem, const void* g) {
    asm volatile("cp.async.cg.shared.global [%0], [%1], 16;" :: "r"(smem), "l"(g) : "memory");
}
__device__ __forceinline__ void cp_commit() {
    asm volatile("cp.async.commit_group;" ::: "memory");
}
template <int N>
__device__ __forceinline__ void cp_wait() {
    asm volatile("cp.async.wait_group %0;" :: "n"(N) : "memory");
}
__device__ __forceinline__ void ldsm_x4(uint32_t addr, uint32_t* r) {
    asm volatile("ldmatrix.sync.aligned.m8n8.x4.shared.b16 {%0,%1,%2,%3}, [%4];"
                 : "=r"(r[0]), "=r"(r[1]), "=r"(r[2]), "=r"(r[3]) : "r"(addr));
}
__device__ __forceinline__ void mma16816(float* d, const uint32_t* a, const uint32_t* b) {
    asm volatile(
        "mma.sync.aligned.m16n8k16.row.col.f32.bf16.bf16.f32 "
        "{%0,%1,%2,%3}, {%4,%5,%6,%7}, {%8,%9}, {%0,%1,%2,%3};\n"
        : "+f"(d[0]), "+f"(d[1]), "+f"(d[2]), "+f"(d[3])
        : "r"(a[0]), "r"(a[1]), "r"(a[2]), "r"(a[3]), "r"(b[0]), "r"(b[1]));
}

// ---------------------------------------------------------------------------
__global__ void k_init(float* out, int out_n) {
    int i = blockIdx.x * blockDim.x + threadIdx.x;
    if (i < 2 * KDIM) g_s[i] = 0.f;
    if (i < out_n)    out[i] = 0.f;
}

// fp32 -> bf16, 8 elements per thread. Destination selected in-kernel (no
// cudaGetSymbolAddress on the host path).
__global__ void k_tobf16(const float4* __restrict__ src, int dstSel, int n8) {
    int i = blockIdx.x * blockDim.x + threadIdx.x;
    if (i >= n8) return;
    __nv_bfloat16* dstp = (dstSel == 0) ? g_x1 : (dstSel == 1) ? g_x2
                        : (dstSel == 2) ? g_wt1 : g_wt2;
    uint4* dst = (uint4*)dstp;
    float4 v0 = src[2 * i], v1 = src[2 * i + 1];
    uint4 o;
    __nv_bfloat162 t;
    t = __floats2bfloat162_rn(v0.x, v0.y); o.x = *(uint32_t*)&t;
    t = __floats2bfloat162_rn(v0.z, v0.w); o.y = *(uint32_t*)&t;
    t = __floats2bfloat162_rn(v1.x, v1.y); o.z = *(uint32_t*)&t;
    t = __floats2bfloat162_rn(v1.z, v1.w); o.w = *(uint32_t*)&t;
    dst[i] = o;
}

__global__ void k_cvec(const float* __restrict__ Wc, const float* __restrict__ ctx,
                       const float* __restrict__ bias, int which) {
    int warp = (blockIdx.x * blockDim.x + threadIdx.x) >> 5;
    int lane = threadIdx.x & 31;
    if (warp >= KDIM) return;
    const float4* wrow = (const float4*)(Wc + (size_t)warp * KDIM);
    const float4* c4   = (const float4*)ctx;
    float sum = 0.f;
#pragma unroll
    for (int it = 0; it < KDIM / 128; ++it) {
        float4 wv = wrow[lane + it * 32];
        float4 cv = c4[lane + it * 32];
        sum += wv.x * cv.x + wv.y * cv.y + wv.z * cv.z + wv.w * cv.w;
    }
#pragma unroll
    for (int o = 16; o; o >>= 1) sum += __shfl_xor_sync(0xffffffffu, sum, o);
    if (lane == 0) g_cvec[which * KDIM + warp] = sum + bias[warp];
}

// ---------------------------------------------------------------------------
// P = elu(X @ Wt.T + cvec). bf16 inputs (preconverted), cp.async 3-stage
// pipeline, ldmatrix + mma.sync. 256 threads = 8 warps of 64x32 tiles.
__global__ __launch_bounds__(256, 2)
void k_proj_mma() {
    extern __shared__ char dynsm[];
    const uint32_t sb = smem_u32(dynsm);

    const int which = blockIdx.z;
    const __nv_bfloat16* __restrict__ X  = which ? g_x2  : g_x1;
    const __nv_bfloat16* __restrict__ Wt = which ? g_wt2 : g_wt1;
    __nv_bfloat16* __restrict__ P = which ? g_p2 : g_p1;
    const float* __restrict__ cvec = g_cvec + which * KDIM;
    float* __restrict__ scol = g_s + which * KDIM;

    const int tid  = threadIdx.x;
    const int wid  = tid >> 5;
    const int lane = tid & 31;
    const int warpRow = wid & 1;        // 0..1 -> rows 64*warpRow
    const int warpCol = wid >> 1;       // 0..3 -> cols 32*warpCol
    const int rowBase = blockIdx.y * BM;
    const int colBase = blockIdx.x * BN;

    // cp.async mapping: idx = tid + it*256; row = idx>>3, kcol = idx&7 (16B units)
    const int cprow = tid >> 3;         // 0..31, advances by 32 per it
    const int cpcol = tid & 7;
    const uint32_t cpswz = (uint32_t)((cpcol ^ (cprow & 7)) << 4);
    const __nv_bfloat16* gA = X  + (size_t)(rowBase + cprow) * KDIM + cpcol * 8;
    const __nv_bfloat16* gB = Wt + (size_t)(colBase + cprow) * KDIM + cpcol * 8;

    // ldmatrix addressing (row&7 == laneQ for all frag rows)
    const int laneQ = lane & 7;
    const int blkId = lane >> 3;
    const uint32_t aKc0 = (uint32_t)(blkId >> 1);    // A kcol low bit
    const uint32_t bKc0 = (uint32_t)(blkId & 1);     // B kcol low bit
    uint32_t aRowOff[4], bRowOff[2];
#pragma unroll
    for (int rb = 0; rb < 4; ++rb)
        aRowOff[rb] = (uint32_t)(warpRow * 64 + rb * 16 + (blkId & 1) * 8 + laneQ) * 128u;
#pragma unroll
    for (int pr = 0; pr < 2; ++pr)
        bRowOff[pr] = (uint32_t)(warpCol * 32 + pr * 16 + (blkId >> 1) * 8 + laneQ) * 128u;

    float acc[4][4][4] = {};

    // issue copy of chunk c into stage s
    auto issue = [&](int s, int c) {
        const uint32_t stg = sb + (uint32_t)s * STAGE_B;
        const int ko = c * KC;
#pragma unroll
        for (int it = 0; it < 4; ++it) {
            uint32_t soff = (uint32_t)(cprow + 32 * it) * 128u + cpswz;
            cp16(stg + soff,          gA + (size_t)(32 * it) * KDIM + ko);
            cp16(stg + TILE_B + soff, gB + (size_t)(32 * it) * KDIM + ko);
        }
        cp_commit();
    };

    issue(0, 0);
    issue(1, 1);

    int stage = 0;
    for (int c = 0; c < NCHUNK; ++c) {
        if (c == NCHUNK - 1) cp_wait<0>(); else cp_wait<1>();
        __syncthreads();

        const uint32_t smA = sb + (uint32_t)stage * STAGE_B;
        const uint32_t smB = smA + TILE_B;
#pragma unroll
        for (int ks = 0; ks < 4; ++ks) {
            uint32_t af[4][4], bf[2][4];
            const uint32_t aSw = (uint32_t)(((ks * 2 + aKc0) ^ laneQ) << 4);
            const uint32_t bSw = (uint32_t)(((ks * 2 + bKc0) ^ laneQ) << 4);
#pragma unroll
            for (int rb = 0; rb < 4; ++rb)
                ldsm_x4(smA + aRowOff[rb] + aSw, af[rb]);
#pragma unroll
            for (int pr = 0; pr < 2; ++pr)
                ldsm_x4(smB + bRowOff[pr] + bSw, bf[pr]);
#pragma unroll
            for (int cf = 0; cf < 4; ++cf) {
                const uint32_t* bp = &bf[cf >> 1][(cf & 1) * 2];
#pragma unroll
                for (int rb = 0; rb < 4; ++rb)
                    mma16816(acc[rb][cf], af[rb], bp);
            }
        }

        if (c + 2 < NCHUNK) issue((stage + 2) % NSTAGE, c + 2);
        stage = (stage + 1) % NSTAGE;
    }

    // ---- epilogue: +cvec, ELU, bf16 store, column sums ----
    const int gq  = lane >> 2;
    const int tig = lane & 3;
    float csum[8];
#pragma unroll
    for (int j = 0; j < 8; ++j) csum[j] = 0.f;

#pragma unroll
    for (int rb = 0; rb < 4; ++rb) {
#pragma unroll
        for (int cf = 0; cf < 4; ++cf) {
            const int col = colBase + warpCol * 32 + cf * 8 + tig * 2;
            const float cv0 = cvec[col], cv1 = cvec[col + 1];
#pragma unroll
            for (int half = 0; half < 2; ++half) {
                const int row = rowBase + warpRow * 64 + rb * 16 + gq + half * 8;
                float v0 = acc[rb][cf][half * 2 + 0] + cv0;
                float v1 = acc[rb][cf][half * 2 + 1] + cv1;
                v0 = (v0 > 0.f) ? v0 : expm1f(v0);
                v1 = (v1 > 0.f) ? v1 : expm1f(v1);
                __nv_bfloat162 pk = __floats2bfloat162_rn(v0, v1);
                *(__nv_bfloat162*)(P + (size_t)row * KDIM + col) = pk;
                csum[cf * 2 + 0] += v0;
                csum[cf * 2 + 1] += v1;
            }
        }
    }
#pragma unroll
    for (int j = 0; j < 8; ++j) {
        float v = csum[j];
        v += __shfl_xor_sync(0xffffffffu, v, 4);
        v += __shfl_xor_sync(0xffffffffu, v, 8);
        v += __shfl_xor_sync(0xffffffffu, v, 16);
        if (gq == 0) {
            int col = colBase + warpCol * 32 + (j >> 1) * 8 + tig * 2 + (j & 1);
            atomicAdd(&scol[col], v);
        }
    }
}

// ---------------------------------------------------------------------------
// logits[z][i] = dot(P[z][i,:], g_s[1-z])  (one warp per row; blockIdx.y = z)
__global__ void k_matvec(int M) {
    int warp = (blockIdx.x * blockDim.x + threadIdx.x) >> 5;
    int lane = threadIdx.x & 31;
    if (warp >= M) return;
    const int z = blockIdx.y;
    const __nv_bfloat16* P = z ? g_p2 : g_p1;
    const uint4* pr = (const uint4*)(P + (size_t)warp * KDIM);
    const float4* s4 = (const float4*)(g_s + (1 - z) * KDIM);
    float sum = 0.f;
#pragma unroll
    for (int it = 0; it < KDIM / 256; ++it) {
        uint4 pk = pr[lane + it * 32];
        float4 sa = s4[(lane + it * 32) * 2 + 0];
        float4 sbv = s4[(lane + it * 32) * 2 + 1];
        float2 p0 = __bfloat1622float2(*(const __nv_bfloat162*)&pk.x);
        float2 p1 = __bfloat1622float2(*(const __nv_bfloat162*)&pk.y);
        float2 p2 = __bfloat1622float2(*(const __nv_bfloat162*)&pk.z);
        float2 p3 = __bfloat1622float2(*(const __nv_bfloat162*)&pk.w);
        sum += p0.x * sa.x + p0.y * sa.y + p1.x * sa.z + p1.y * sa.w;
        sum += p2.x * sbv.x + p2.y * sbv.y + p3.x * sbv.z + p3.y * sbv.w;
    }
#pragma unroll
    for (int o = 16; o; o >>= 1) sum += __shfl_xor_sync(0xffffffffu, sum, o);
    if (lane == 0) g_logits[z * A_MAX + warp] = sum;
}

// softmax over n logits; blockIdx.x = which
__global__ void k_softmax(int n) {
    __shared__ float sbuf[1024];
    const int which = blockIdx.x;
    const float* logits = g_logits + which * A_MAX;
    float* w = g_w + which * A_MAX;
    int tid = threadIdx.x;

    float mx = -3.4e38f;
    for (int i = tid; i < n; i += 1024) mx = fmaxf(mx, logits[i]);
    sbuf[tid] = mx; __syncthreads();
    for (int o = 512; o; o >>= 1) {
        if (tid < o) sbuf[tid] = fmaxf(sbuf[tid], sbuf[tid + o]);
        __syncthreads();
    }
    mx = sbuf[0]; __syncthreads();

    float se = 0.f;
    for (int i = tid; i < n; i += 1024) se += expf(logits[i] - mx);
    sbuf[tid] = se; __syncthreads();
    for (int o = 512; o; o >>= 1) {
        if (tid < o) sbuf[tid] += sbuf[tid + o];
        __syncthreads();
    }
    float inv = 1.f / sbuf[0];

    for (int i = tid; i < n; i += 1024) w[i] = expf(logits[i] - mx) * inv;
}

// out[z*KDIM + col4] += sum_r w[z][r] * seq_z[r, col4]; float4 per thread
__global__ void k_pool(const float* __restrict__ seq1, const float* __restrict__ seq2,
                       float* __restrict__ out, int rowsPerBlock) {
    const int z = blockIdx.z;
    const float* seq = z ? seq2 : seq1;
    const float* w = g_w + z * A_MAX;
    const int c4 = threadIdx.x;           // 0..255 -> cols c4*4
    const int r0 = blockIdx.y * rowsPerBlock;
    float4 acc = {0.f, 0.f, 0.f, 0.f};
    for (int r = r0; r < r0 + rowsPerBlock; ++r) {
        float wr = w[r];
        float4 v = *(const float4*)(seq + (size_t)r * KDIM + c4 * 4);
        acc.x += wr * v.x; acc.y += wr * v.y; acc.z += wr * v.z; acc.w += wr * v.w;
    }
    float* o = out + z * KDIM + c4 * 4;
    atomicAdd(o + 0, acc.x);
    atomicAdd(o + 1, acc.y);
    atomicAdd(o + 2, acc.z);
    atomicAdd(o + 3, acc.w);
}

// ---------------------------------------------------------------------------
extern "C" void kernel_launch(void* const* d_in, const int* in_sizes, int n_in,
                              void* d_out, int out_size) {
    const float* seq1 = (const float*)d_in[0];
    const float* seq2 = (const float*)d_in[1];
    const float* ctx  = (const float*)d_in[2];
    const float* Wc1  = (const float*)d_in[3];
    const float* W1   = (const float*)d_in[4];
    const float* b1   = (const float*)d_in[5];
    const float* Wc2  = (const float*)d_in[6];
    const float* W2   = (const float*)d_in[7];
    const float* b2   = (const float*)d_in[8];
    float* out = (float*)d_out;

    const int a = in_sizes[0] / KDIM;   // 8192
    const int b = in_sizes[1] / KDIM;   // 8192

    cudaFuncSetAttribute(k_proj_mma, cudaFuncAttributeMaxDynamicSharedMemorySize, SMEM_DYN);

    k_init<<<(2 * KDIM + 255) / 256, 256>>>(out, out_size);

    k_cvec<<<KDIM / 8, 256>>>(Wc1, ctx, b1, 0);
    k_cvec<<<KDIM / 8, 256>>>(Wc2, ctx, b2, 1);

    {   // fp32 -> bf16 conversions (dest chosen in-kernel)
        const int nseq8 = a * KDIM / 8, nw8 = KDIM * KDIM / 8;
        k_tobf16<<<(nseq8 + 255) / 256, 256>>>((const float4*)seq1, 0, nseq8);
        k_tobf16<<<(nseq8 + 255) / 256, 256>>>((const float4*)seq2, 1, nseq8);
        k_tobf16<<<(nw8 + 255) / 256, 256>>>((const float4*)W1, 2, nw8);
        k_tobf16<<<(nw8 + 255) / 256, 256>>>((const float4*)W2, 3, nw8);
    }

    {
        dim3 g(KDIM / BN, a / BM, 2);
        k_proj_mma<<<g, 256, SMEM_DYN>>>();
    }

    {
        dim3 gm((a + 7) / 8, 2);
        k_matvec<<<gm, 256>>>(a);
    }

    k_softmax<<<2, 1024>>>(a);

    {
        const int RPB = 64;
        dim3 gp(1, a / RPB, 2);
        k_pool<<<gp, 256>>>(seq1, seq2, out, RPB);
    }
}